// round 16
// baseline (speedup 1.0000x reference)
#include <cuda_runtime.h>
#include <cuda_fp16.h>
#include <cstdint>

// out[b,i] = sum_h W2[i,h] * relu( sum_d X[b,d]*Adj[i,d]*W1[i,h,d] )
// B=16384, D=64, H=64.
//
// Single-term fp16 HMMA (mma.sync m16n8k16 f32.f16.f16).
// Block = (1 node x 512 rows) = 4 tiles of 128 rows (2048 blocks = 6.9
// waves -> small tail); 8 warps; warp = 16-row strip, all 64 h.
// B fragments loaded ONCE per warp with 16 direct LDG.128 from prep-emitted
// fragment-order Wfrag_g (no smem bounce, NO block-wide barrier anywhere).
// X strips warp-private, double-buffered cp.async + ldsm. Epilogue on the
// tensor pipe (relu->pack->2 split MMA chains + FADD merge).

#define NT   256
#define TB   128
#define TPB  4      // tiles per block

// ---- device-global buffers (prep output) ----
static __device__ __align__(16) __half Xf_g[16384 * 64];      // linear fp16 X
static __device__ __align__(16) uint4  Wfrag_g[64 * 16 * 32]; // frag-order W'

static __device__ __forceinline__ uint32_t h2u(__half2 h) {
    return *(uint32_t*)&h;
}

static __device__ __forceinline__ uint32_t smem_u32(const void* p) {
    uint32_t a;
    asm("{ .reg .u64 t; cvta.to.shared.u64 t, %1; cvt.u32.u64 %0, t; }" : "=r"(a) : "l"(p));
    return a;
}

static __device__ __forceinline__ void cp16(uint32_t dst, const void* src) {
    asm volatile("cp.async.ca.shared.global [%0], [%1], 16;"
                 :: "r"(dst), "l"(src) : "memory");
}

static __device__ __forceinline__ void ldsm4(uint32_t* r, uint32_t addr) {
    asm volatile("ldmatrix.sync.aligned.m8n8.x4.shared.b16 {%0,%1,%2,%3}, [%4];"
                 : "=r"(r[0]), "=r"(r[1]), "=r"(r[2]), "=r"(r[3]) : "r"(addr));
}

static __device__ __forceinline__ void mma16816(float* c, const uint32_t* a,
                                                const uint32_t* b) {
    asm volatile(
        "mma.sync.aligned.m16n8k16.row.col.f32.f16.f16.f32 "
        "{%0,%1,%2,%3}, {%4,%5,%6,%7}, {%8,%9}, {%0,%1,%2,%3};"
        : "+f"(c[0]), "+f"(c[1]), "+f"(c[2]), "+f"(c[3])
        : "r"(a[0]), "r"(a[1]), "r"(a[2]), "r"(a[3]), "r"(b[0]), "r"(b[1]));
}

// pack two f32 -> half2 with relu (F2FP.PACK + one HMNMX2)
static __device__ __forceinline__ uint32_t packrelu(float a, float b) {
    __half2 h = __floats2half2_rn(a, b);
    __half2 z = __float2half2_rn(0.f);
    return h2u(__hmax2(h, z));
}

// ---- prep: X -> linear fp16; W1*adj -> fragment-order fp16 ----
__global__ __launch_bounds__(NT)
void prep_kernel(const float* __restrict__ X,
                 const float* __restrict__ Adj,
                 const float* __restrict__ W1)
{
    int gid = blockIdx.x * NT + threadIdx.x;
    if (gid < 262144) {                       // X: 16384*64/4 float4s
        float4 v = ((const float4*)X)[gid];
        uint2 r;
        r.x = h2u(__floats2half2_rn(v.x, v.y));
        r.y = h2u(__floats2half2_rn(v.z, v.w));
        ((uint2*)Xf_g)[gid] = r;
    } else if (gid < 262144 + 32768) {
        // W fragments: j = (node*16 + w)*32 + l ; flat word = ks*16 + n*2 + r
        int j    = gid - 262144;
        int l    = j & 31;
        int w    = (j >> 5) & 15;
        int node = j >> 9;
        int gi = l >> 2, ti = l & 3;
        uint32_t vv[4];
        #pragma unroll
        for (int q = 0; q < 4; ++q) {
            int idx = w * 4 + q;
            int ks = idx >> 4, ng = (idx >> 1) & 7, r = idx & 1;
            int h0 = ng * 8 + gi;
            int d0 = ks * 16 + ti * 2 + r * 8;
            const float* w1p = W1 + ((size_t)node * 64 + h0) * 64;
            const float* ap  = Adj + node * 64;
            vv[q] = h2u(__floats2half2_rn(w1p[d0] * ap[d0],
                                          w1p[d0 + 1] * ap[d0 + 1]));
        }
        uint4 o; o.x = vv[0]; o.y = vv[1]; o.z = vv[2]; o.w = vv[3];
        Wfrag_g[j] = o;
    }
}

// stage one 16-row strip of a tile into a warp buffer (4 cp16 per lane)
static __device__ __forceinline__ void stage_strip(uint32_t xdst,
                                                   const char* xsrc, int l) {
    #pragma unroll
    for (int it = 0; it < 4; ++it) {
        int c  = l + it * 32;               // 0..127
        int rl = c >> 3, k16 = c & 7;       // row-in-strip, 16B chunk
        cp16(xdst + rl * 128 + ((k16 ^ (rl & 7)) << 4),
             xsrc + (size_t)rl * 128 + k16 * 16);
    }
}

// ---- main GEMM ----
__global__ __launch_bounds__(NT, 2)
void tp_kernel(const float* __restrict__ W2, float* __restrict__ out)
{
    __shared__ __align__(16) char smem[8 * 2 * 2048];   // X strips only, 32KB
    const uint32_t sb = smem_u32(smem);
    const int tid = threadIdx.x;
    const int wid = tid >> 5;
    const int l   = tid & 31;
    const int i    = blockIdx.x;                // node (fastest -> X L2 reuse)
    const int row0 = blockIdx.y * (TB * TPB);   // 512-row group

    const uint32_t xwarp = sb + wid * 4096;     // warp-private 2x2KB
    const char* xbase = (const char*)(Xf_g + (size_t)(row0 + wid * 16) * 64);

    // ---- B fragments FIRST: 16 direct LDG.128 (latency overlaps staging) ----
    uint4 wraw[16];
    {
        const uint4* wp = Wfrag_g + i * 512 + l;
        #pragma unroll
        for (int w = 0; w < 16; ++w)
            wraw[w] = __ldg(wp + w * 32);
    }

    // ---- X tile 0 (own strip) ----
    stage_strip(xwarp, xbase, l);
    asm volatile("cp.async.commit_group;" ::: "memory");

    // ---- W2 epilogue B fragments: only n-col 0 populated (lanes l<4) ----
    uint32_t b2[4][2];
    {
        const float* w2p = W2 + i * 64;
        #pragma unroll
        for (int kc = 0; kc < 4; ++kc) {
            if (l < 4) {
                b2[kc][0] = h2u(__floats2half2_rn(w2p[kc * 16 + 2 * l],
                                                  w2p[kc * 16 + 2 * l + 1]));
                b2[kc][1] = h2u(__floats2half2_rn(w2p[kc * 16 + 8 + 2 * l],
                                                  w2p[kc * 16 + 8 + 2 * l + 1]));
            } else {
                b2[kc][0] = 0u;
                b2[kc][1] = 0u;
            }
        }
    }

    // unpack resident B fragments
    uint32_t wv[64];
    #pragma unroll
    for (int w = 0; w < 16; ++w) {
        wv[w * 4 + 0] = wraw[w].x; wv[w * 4 + 1] = wraw[w].y;
        wv[w * 4 + 2] = wraw[w].z; wv[w * 4 + 3] = wraw[w].w;
    }

    // A geometry: 16 rows in own strip
    const int arow = l & 15;
    const uint32_t asw   = arow & 7;
    const uint32_t ahalf = (l >> 4) & 1;

    #pragma unroll
    for (int t = 0; t < TPB; ++t) {
        // own fill of tile t complete; make visible warp-wide
        asm volatile("cp.async.wait_group 0;" ::: "memory");
        __syncwarp();

        // prefetch own strip of tile t+1 (overlaps this tile's MMAs)
        if (t + 1 < TPB) {
            stage_strip(xwarp + (((t + 1) & 1) ? 2048u : 0u),
                        xbase + (size_t)(t + 1) * TB * 128, l);
            asm volatile("cp.async.commit_group;" ::: "memory");
        }

        const uint32_t aoff = xwarp + (uint32_t)((t & 1) * 2048) + arow * 128;

        float acc[8][4];
        #pragma unroll
        for (int n = 0; n < 8; ++n)
            #pragma unroll
            for (int q = 0; q < 4; ++q) acc[n][q] = 0.f;

        #pragma unroll
        for (int ks = 0; ks < 4; ++ks) {
            uint32_t xv[4];
            ldsm4(xv, aoff + (((ks * 2 + ahalf) ^ asw) << 4));
            #pragma unroll
            for (int n = 0; n < 8; ++n)
                mma16816(acc[n], xv, &wv[ks * 16 + n * 2]);
        }

        // ---- epilogue on tensor pipe: out = relu(H) @ W2 ----
        // two independent accumulator chains, merged with FADD
        float co0[4] = {0.f, 0.f, 0.f, 0.f};
        float co1[4] = {0.f, 0.f, 0.f, 0.f};
        #pragma unroll
        for (int kc = 0; kc < 4; ++kc) {
            uint32_t af[4];
            af[0] = packrelu(acc[2 * kc][0],     acc[2 * kc][1]);
            af[1] = packrelu(acc[2 * kc][2],     acc[2 * kc][3]);
            af[2] = packrelu(acc[2 * kc + 1][0], acc[2 * kc + 1][1]);
            af[3] = packrelu(acc[2 * kc + 1][2], acc[2 * kc + 1][3]);
            mma16816((kc & 1) ? co1 : co0, af, b2[kc]);
        }
        // col 0 lives in lanes l%4==0: row l/4 and row l/4+8
        if ((l & 3) == 0) {
            int grow = row0 + t * TB + wid * 16 + (l >> 2);
            out[(size_t)grow * 64 + i]       = co0[0] + co1[0];
            out[(size_t)(grow + 8) * 64 + i] = co0[2] + co1[2];
        }
    }
}

extern "C" void kernel_launch(void* const* d_in, const int* in_sizes, int n_in,
                              void* d_out, int out_size) {
    const float* X   = (const float*)d_in[0];  // [16384, 64]
    const float* Adj = (const float*)d_in[1];  // [64, 64]
    const float* W1  = (const float*)d_in[2];  // [64, 64, 64] (i,h,d)
    const float* W2  = (const float*)d_in[3];  // [64, 64]
    float* out = (float*)d_out;                // [16384, 64]

    prep_kernel<<<1152, NT>>>(X, Adj, W1);

    dim3 grid(64, 16384 / (TB * TPB));
    tp_kernel<<<grid, NT>>>(W2, out);
}

// round 17
// speedup vs baseline: 1.1323x; 1.1323x over previous
#include <cuda_runtime.h>
#include <cuda_fp16.h>
#include <cstdint>

// out[b,i] = sum_h W2[i,h] * relu( sum_d X[b,d]*Adj[i,d]*W1[i,h,d] )
// B=16384, D=64, H=64.
//
// Single-term fp16 HMMA (mma.sync m16n8k16 f32.f16.f16).
// PERSISTENT single-wave grid: 296 blocks (148 SM x 2 CTA), work = 8192
// items (node, 128-row tile) split into contiguous (node-major) ranges of
// 27-28 items -> B fragments reload only on node change (<=2x per block),
// zero tail wave. Warp = 16-row strip, all 64 h; B register-resident via
// 16 LDG.128 from fragment-order Wfrag_g; X strips warp-private,
// double-buffered cp.async + ldsm; epilogue on the tensor pipe.

#define NT     256
#define TB     128
#define NBLK   296
#define NITEMS 8192   // 64 nodes x 128 tiles

// ---- device-global buffers (prep output) ----
static __device__ __align__(16) __half Xf_g[16384 * 64];      // linear fp16 X
static __device__ __align__(16) uint4  Wfrag_g[64 * 16 * 32]; // frag-order W'

static __device__ __forceinline__ uint32_t h2u(__half2 h) {
    return *(uint32_t*)&h;
}

static __device__ __forceinline__ uint32_t smem_u32(const void* p) {
    uint32_t a;
    asm("{ .reg .u64 t; cvta.to.shared.u64 t, %1; cvt.u32.u64 %0, t; }" : "=r"(a) : "l"(p));
    return a;
}

static __device__ __forceinline__ void cp16(uint32_t dst, const void* src) {
    asm volatile("cp.async.ca.shared.global [%0], [%1], 16;"
                 :: "r"(dst), "l"(src) : "memory");
}

static __device__ __forceinline__ void ldsm4(uint32_t* r, uint32_t addr) {
    asm volatile("ldmatrix.sync.aligned.m8n8.x4.shared.b16 {%0,%1,%2,%3}, [%4];"
                 : "=r"(r[0]), "=r"(r[1]), "=r"(r[2]), "=r"(r[3]) : "r"(addr));
}

static __device__ __forceinline__ void mma16816(float* c, const uint32_t* a,
                                                const uint32_t* b) {
    asm volatile(
        "mma.sync.aligned.m16n8k16.row.col.f32.f16.f16.f32 "
        "{%0,%1,%2,%3}, {%4,%5,%6,%7}, {%8,%9}, {%0,%1,%2,%3};"
        : "+f"(c[0]), "+f"(c[1]), "+f"(c[2]), "+f"(c[3])
        : "r"(a[0]), "r"(a[1]), "r"(a[2]), "r"(a[3]), "r"(b[0]), "r"(b[1]));
}

// pack two f32 -> half2 with relu
static __device__ __forceinline__ uint32_t packrelu(float a, float b) {
    __half2 h = __floats2half2_rn(a, b);
    __half2 z = __float2half2_rn(0.f);
    return h2u(__hmax2(h, z));
}

// ---- prep: X -> linear fp16; W1*adj -> fragment-order fp16 ----
__global__ __launch_bounds__(NT)
void prep_kernel(const float* __restrict__ X,
                 const float* __restrict__ Adj,
                 const float* __restrict__ W1)
{
    int gid = blockIdx.x * NT + threadIdx.x;
    if (gid < 262144) {                       // X: 16384*64/4 float4s
        float4 v = ((const float4*)X)[gid];
        uint2 r;
        r.x = h2u(__floats2half2_rn(v.x, v.y));
        r.y = h2u(__floats2half2_rn(v.z, v.w));
        ((uint2*)Xf_g)[gid] = r;
    } else if (gid < 262144 + 32768) {
        // W fragments: j = (node*16 + w)*32 + l ; flat word = ks*16 + n*2 + r
        int j    = gid - 262144;
        int l    = j & 31;
        int w    = (j >> 5) & 15;
        int node = j >> 9;
        int gi = l >> 2, ti = l & 3;
        uint32_t vv[4];
        #pragma unroll
        for (int q = 0; q < 4; ++q) {
            int idx = w * 4 + q;
            int ks = idx >> 4, ng = (idx >> 1) & 7, r = idx & 1;
            int h0 = ng * 8 + gi;
            int d0 = ks * 16 + ti * 2 + r * 8;
            const float* w1p = W1 + ((size_t)node * 64 + h0) * 64;
            const float* ap  = Adj + node * 64;
            vv[q] = h2u(__floats2half2_rn(w1p[d0] * ap[d0],
                                          w1p[d0 + 1] * ap[d0 + 1]));
        }
        uint4 o; o.x = vv[0]; o.y = vv[1]; o.z = vv[2]; o.w = vv[3];
        Wfrag_g[j] = o;
    }
}

// stage one 16-row strip of a tile into a warp buffer (4 cp16 per lane)
static __device__ __forceinline__ void stage_strip(uint32_t xdst,
                                                   const char* xsrc, int l) {
    #pragma unroll
    for (int it = 0; it < 4; ++it) {
        int c  = l + it * 32;               // 0..127
        int rl = c >> 3, k16 = c & 7;       // row-in-strip, 16B chunk
        cp16(xdst + rl * 128 + ((k16 ^ (rl & 7)) << 4),
             xsrc + (size_t)rl * 128 + k16 * 16);
    }
}

// ---- main GEMM (persistent single wave) ----
__global__ __launch_bounds__(NT, 2)
void tp_kernel(const float* __restrict__ W2, float* __restrict__ out)
{
    __shared__ __align__(16) char smem[8 * 2 * 2048];   // X strips, 32KB
    const uint32_t sb = smem_u32(smem);
    const int tid = threadIdx.x;
    const int wid = tid >> 5;
    const int l   = tid & 31;
    const int bid = blockIdx.x;

    const int start = (bid * NITEMS) / NBLK;
    const int end   = ((bid + 1) * NITEMS) / NBLK;

    const uint32_t xwarp = sb + wid * 4096;   // warp-private 2x2KB
    const char* Xb = (const char*)Xf_g + (size_t)wid * 16 * 128;

    // A geometry: 16 rows in own strip
    const int arow = l & 15;
    const uint32_t asw   = arow & 7;
    const uint32_t ahalf = (l >> 4) & 1;

    // ---- stage first item's X strip ----
    {
        int tile0 = start & 127;
        stage_strip(xwarp + (uint32_t)((start & 1) * 2048),
                    Xb + (size_t)tile0 * TB * 128, l);
        asm volatile("cp.async.commit_group;" ::: "memory");
    }

    int cur_node = -1;
    uint32_t wv[64];
    uint32_t b2[4][2];

    for (int it = start; it < end; ++it) {
        const int node = it >> 7;
        const int tile = it & 127;

        // own fill of this item's strip complete
        asm volatile("cp.async.wait_group 0;" ::: "memory");
        __syncwarp();

        // prefetch next item's strip (overlaps this item's work)
        if (it + 1 < end) {
            int tn = (it + 1) & 127;
            stage_strip(xwarp + (uint32_t)(((it + 1) & 1) * 2048),
                        Xb + (size_t)tn * TB * 128, l);
            asm volatile("cp.async.commit_group;" ::: "memory");
        }

        // ---- B fragments + W2 reload on node change (<=2x per block) ----
        if (node != cur_node) {
            cur_node = node;
            const uint4* wp = Wfrag_g + node * 512 + l;
            #pragma unroll
            for (int w = 0; w < 16; ++w) {
                uint4 t = __ldg(wp + w * 32);
                wv[w * 4 + 0] = t.x; wv[w * 4 + 1] = t.y;
                wv[w * 4 + 2] = t.z; wv[w * 4 + 3] = t.w;
            }
            const float* w2p = W2 + node * 64;
            #pragma unroll
            for (int kc = 0; kc < 4; ++kc) {
                if (l < 4) {
                    b2[kc][0] = h2u(__floats2half2_rn(w2p[kc * 16 + 2 * l],
                                                      w2p[kc * 16 + 2 * l + 1]));
                    b2[kc][1] = h2u(__floats2half2_rn(w2p[kc * 16 + 8 + 2 * l],
                                                      w2p[kc * 16 + 8 + 2 * l + 1]));
                } else {
                    b2[kc][0] = 0u;
                    b2[kc][1] = 0u;
                }
            }
        }

        const uint32_t aoff = xwarp + (uint32_t)((it & 1) * 2048) + arow * 128;

        float acc[8][4];
        #pragma unroll
        for (int n = 0; n < 8; ++n)
            #pragma unroll
            for (int q = 0; q < 4; ++q) acc[n][q] = 0.f;

        #pragma unroll
        for (int ks = 0; ks < 4; ++ks) {
            uint32_t xv[4];
            ldsm4(xv, aoff + (((ks * 2 + ahalf) ^ asw) << 4));
            #pragma unroll
            for (int n = 0; n < 8; ++n)
                mma16816(acc[n], xv, &wv[ks * 16 + n * 2]);
        }

        // ---- epilogue on tensor pipe: out = relu(H) @ W2 ----
        float co0[4] = {0.f, 0.f, 0.f, 0.f};
        float co1[4] = {0.f, 0.f, 0.f, 0.f};
        #pragma unroll
        for (int kc = 0; kc < 4; ++kc) {
            uint32_t af[4];
            af[0] = packrelu(acc[2 * kc][0],     acc[2 * kc][1]);
            af[1] = packrelu(acc[2 * kc][2],     acc[2 * kc][3]);
            af[2] = packrelu(acc[2 * kc + 1][0], acc[2 * kc + 1][1]);
            af[3] = packrelu(acc[2 * kc + 1][2], acc[2 * kc + 1][3]);
            mma16816((kc & 1) ? co1 : co0, af, b2[kc]);
        }
        // col 0 lives in lanes l%4==0: row l/4 and row l/4+8
        if ((l & 3) == 0) {
            int grow = tile * TB + wid * 16 + (l >> 2);
            out[(size_t)grow * 64 + node]       = co0[0] + co1[0];
            out[(size_t)(grow + 8) * 64 + node] = co0[2] + co1[2];
        }
    }
}

extern "C" void kernel_launch(void* const* d_in, const int* in_sizes, int n_in,
                              void* d_out, int out_size) {
    const float* X   = (const float*)d_in[0];  // [16384, 64]
    const float* Adj = (const float*)d_in[1];  // [64, 64]
    const float* W1  = (const float*)d_in[2];  // [64, 64, 64] (i,h,d)
    const float* W2  = (const float*)d_in[3];  // [64, 64]
    float* out = (float*)d_out;                // [16384, 64]

    prep_kernel<<<1152, NT>>>(X, Adj, W1);

    tp_kernel<<<NBLK, NT>>>(W2, out);
}